// round 9
// baseline (speedup 1.0000x reference)
#include <cuda_runtime.h>
#include <stdint.h>

#define NB      8
#define NF4     65536             // float4 groups per sample
#define NBINS   2048
#define MARGIN  4500              // >7 sigma of 1/4-subsample count noise
#define SCALE_D 65535.0f          // d  in [0,1]
#define SCALE_C 21845.0f          // dc in [0,3]

__device__ uint4    g_pk   [NB * NF4];      // 8MB packed bf16x2 scratch (L2-resident)
__device__ unsigned g_hist1[2][NB][NBINS];  // subsampled linear-key histogram
__device__ unsigned g_win  [2][NB][NBINS];  // exact window counts
__device__ float    g_wsum [2][NB][NBINS];  // exact window sums
__device__ unsigned g_cntU [NB];
__device__ float    g_Sab  [2][NB];
__device__ unsigned g_Cab  [2][NB];
__device__ int      g_wlo  [2][NB];
__device__ int      g_whi  [2][NB];

__device__ __forceinline__ unsigned f2bf(float f) {   // RNE f32->bf16 bits (nonneg finite)
    unsigned u = __float_as_uint(f);
    return (u + 0x7FFFu + ((u >> 16) & 1u)) >> 16;
}
__device__ __forceinline__ float bf2f(unsigned b) { return __uint_as_float(b << 16); }
__device__ __forceinline__ int   qkey(float v, float s) {
    int q = (int)(v * s);
    return q > 65535 ? 65535 : q;
}
__device__ __forceinline__ float pget(const float4& v, int p) { return p == 0 ? v.x : p == 1 ? v.y : p == 2 ? v.z : v.w; }
__device__ __forceinline__ int   tget(const int4&   v, int p) { return p == 0 ? v.x : p == 1 ? v.y : p == 2 ? v.z : v.w; }

// ===========================================================================
// K1: streaming pass. 2048 blocks x 256 thr, ONE float4 group per thread.
//     15 independent LDG.128 per thread -> max MLP; no launch-bounds reg cap.
// ===========================================================================
__global__ void k1(const float4* __restrict__ img, const float4* __restrict__ alp,
                   const float4* __restrict__ prd, const int4*   __restrict__ tri,
                   const float4* __restrict__ fg,  const float4* __restrict__ bg,
                   float* __restrict__ out)
{
    const int t   = threadIdx.x;
    const int blk = blockIdx.x;
    const int b   = blk >> 8;                 // 256 blocks per sample
    const int gl  = ((blk & 255) << 8) + t;   // group within sample
    const int g   = b * NF4 + gl;
    const int cb  = b * 3 * NF4;

    if (blk == 0 && t == 0) out[0] = 0.0f;

    int4   tv = tri[g];
    float4 av = alp[g], pv = prd[g];
    float4 i0 = img[cb + gl], i1 = img[cb + NF4 + gl], i2 = img[cb + 2 * NF4 + gl];
    float4 f0 = fg [cb + gl], f1 = fg [cb + NF4 + gl], f2 = fg [cb + 2 * NF4 + gl];
    float4 g0 = bg [cb + gl], g1 = bg [cb + NF4 + gl], g2 = bg [cb + 2 * NF4 + gl];

    const float inv255 = 1.0f / 255.0f;
    unsigned pk[4];
    unsigned cnt = 0;
    float d0 = 0.f, dc0 = 0.f;
    bool u0 = false;
#pragma unroll
    for (int p = 0; p < 4; p++) {
        bool u = (tget(tv, p) == 128);
        float pr = pget(pv, p), q = 1.0f - pr;
        float d = 0.0f, dc = 0.0f;
        if (u) {
            d  = fabsf(pget(av, p) * inv255 - pr);
            dc = fabsf(pget(i0, p) - (pget(f0, p) * pr + q * pget(g0, p)))
               + fabsf(pget(i1, p) - (pget(f1, p) * pr + q * pget(g1, p)))
               + fabsf(pget(i2, p) - (pget(f2, p) * pr + q * pget(g2, p)));
            cnt++;
        }
        if (p == 0) { u0 = u; d0 = d; dc0 = dc; }
        pk[p] = f2bf(d) | (f2bf(dc) << 16);
    }

    if (u0) {                                  // 1/4 subsample, linear keys: no hot bins
        atomicAdd(&g_hist1[0][b][qkey(d0,  SCALE_D) >> 5], 1u);
        atomicAdd(&g_hist1[1][b][qkey(dc0, SCALE_C) >> 5], 1u);
    }
    g_pk[g] = make_uint4(pk[0], pk[1], pk[2], pk[3]);

    // per-block unknown count -> one REDG per block
    const int l = t & 31, w = t >> 5;
    for (int o = 16; o; o >>= 1) cnt += __shfl_down_sync(0xffffffffu, cnt, o);
    __shared__ unsigned s_ru[8];
    if (l == 0) s_ru[w] = cnt;
    __syncthreads();
    if (t == 0) {
        unsigned tot = 0;
#pragma unroll
        for (int i = 0; i < 8; i++) tot += s_ru[i];
        atomicAdd(&g_cntU[b], tot);
    }
}

// ===========================================================================
// K2: select conservative window per (array, sample); self-zero histogram.
// ===========================================================================
__global__ void __launch_bounds__(256) k2()
{
    const int a = blockIdx.x >> 3, b = blockIdx.x & 7;
    const int t = threadIdx.x, l = t & 31, w = t >> 5;
    __shared__ unsigned sh[NBINS];
    __shared__ unsigned wt[8];

    for (int i = t; i < NBINS; i += 256) {
        sh[i] = g_hist1[a][b][i];
        g_hist1[a][b][i] = 0u;                 // self-clean for next replay
    }
    __syncthreads();

    unsigned count = g_cntU[b];
    int k = (int)floorf((float)count * 0.7f);
    if (k <= 0) {
        if (t == 0) { g_wlo[a][b] = 2047; g_whi[a][b] = -1; }
        return;
    }
    unsigned harr[8];
    unsigned loc = 0;
#pragma unroll
    for (int jj = 0; jj < 8; jj++) { harr[jj] = sh[t * 8 + jj]; loc += harr[jj]; }
    unsigned s = loc;
#pragma unroll
    for (int o = 1; o < 32; o <<= 1) {         // warp inclusive suffix scan
        unsigned v = __shfl_down_sync(0xffffffffu, s, o);
        if (l + o < 32) s += v;
    }
    if (l == 0) wt[w] = s;
    __syncthreads();
    unsigned wsuf = 0;
    for (int w2 = w + 1; w2 < 8; w2++) wsuf += wt[w2];
    int acc = (int)(wsuf + (s - loc));         // subsampled count above bin t*8+7
    int tLo = k + MARGIN;
    int tHi = max(k - MARGIN, 1);
#pragma unroll
    for (int jj = 7; jj >= 0; jj--) {
        int i = t * 8 + jj;
        int c = (int)harr[jj];
        int above  = 4 * acc;                  // estimated exact count above bin i
        int aboveP = 4 * (acc + c);            // estimated above bin i-1
        if (above < tLo && (i == 0 || aboveP >= tLo)) g_wlo[a][b] = i;
        if (above < tHi && (i == 0 || aboveP >= tHi)) g_whi[a][b] = i;
        acc += c;
    }
}

// ===========================================================================
// K3: re-walk 8MB scratch (L2-hot). Exact above-window sum/count + window hist.
// ===========================================================================
__global__ void __launch_bounds__(256) k3()
{
    const int t = threadIdx.x;
    const int g = blockIdx.x * 256 + t;
    const int b = g >> 16;                     // NF4 = 65536 groups per sample

    const int wloD = g_wlo[0][b], whiD = g_whi[0][b];
    const int wloC = g_wlo[1][b], whiC = g_whi[1][b];
    const int hiD = (whiD + 1) << 5, loD = max(wloD << 5, 1);
    const int hiC = (whiC + 1) << 5, loC = max(wloC << 5, 1);

    uint4 pv4 = g_pk[g];
    unsigned pk4[4] = { pv4.x, pv4.y, pv4.z, pv4.w };

    float s0 = 0.0f, s1 = 0.0f;
    unsigned c0 = 0, c1 = 0;
#pragma unroll
    for (int p = 0; p < 4; p++) {
        float vd = bf2f(pk4[p] & 0xFFFFu);
        float vc = bf2f(pk4[p] >> 16);
        int kqd = qkey(vd, SCALE_D);
        int kqc = qkey(vc, SCALE_C);
        if (kqd >= hiD) { s0 += vd; c0++; }
        else if (kqd >= loD) {
            int idx = (kqd >> 5) - wloD;
            atomicAdd(&g_win[0][b][idx], 1u);
            atomicAdd(&g_wsum[0][b][idx], vd);
        }
        if (kqc >= hiC) { s1 += vc; c1++; }
        else if (kqc >= loC) {
            int idx = (kqc >> 5) - wloC;
            atomicAdd(&g_win[1][b][idx], 1u);
            atomicAdd(&g_wsum[1][b][idx], vc);
        }
    }
    const int l = t & 31, w = t >> 5;
    for (int o = 16; o; o >>= 1) {
        s0 += __shfl_down_sync(0xffffffffu, s0, o);
        s1 += __shfl_down_sync(0xffffffffu, s1, o);
        c0 += __shfl_down_sync(0xffffffffu, c0, o);
        c1 += __shfl_down_sync(0xffffffffu, c1, o);
    }
    __shared__ float    sf0[8], sf1[8];
    __shared__ unsigned sc0[8], sc1[8];
    if (l == 0) { sf0[w] = s0; sf1[w] = s1; sc0[w] = c0; sc1[w] = c1; }
    __syncthreads();
    if (t == 0) {
        float a0 = 0.f, a1 = 0.f; unsigned b0 = 0, b1 = 0;
#pragma unroll
        for (int i = 0; i < 8; i++) { a0 += sf0[i]; a1 += sf1[i]; b0 += sc0[i]; b1 += sc1[i]; }
        atomicAdd(&g_Sab[0][b], a0);  atomicAdd(&g_Sab[1][b], a1);
        atomicAdd(&g_Cab[0][b], b0);  atomicAdd(&g_Cab[1][b], b1);
    }
}

// ===========================================================================
// K4: finalize 16 units; full state cleanup for next graph replay.
// ===========================================================================
__global__ void __launch_bounds__(256) k4(float* __restrict__ out)
{
    const int a = blockIdx.x >> 3, b = blockIdx.x & 7;
    const int t = threadIdx.x, l = t & 31, w = t >> 5;
    __shared__ unsigned shc[NBINS];
    __shared__ float    shs[NBINS];
    __shared__ unsigned wt[8];
    __shared__ float    wtf[8];

    unsigned cc = g_cntU[b];
    int kk = (int)floorf((float)cc * 0.7f);
    int wlo = g_wlo[a][b], whi = g_whi[a][b];

    for (int i = t; i < NBINS; i += 256) {
        shc[i] = g_win[a][b][i];
        shs[i] = g_wsum[a][b][i];
        g_win[a][b][i] = 0u;                   // self-clean
        g_wsum[a][b][i] = 0.f;
    }
    __syncthreads();

    if (kk > 0 && whi >= wlo) {
        unsigned lc = 0; float lv = 0.f;
#pragma unroll
        for (int jj = 0; jj < 8; jj++) { lc += shc[t * 8 + jj]; lv += shs[t * 8 + jj]; }
        unsigned sc = lc; float sv = lv;
#pragma unroll
        for (int o = 1; o < 32; o <<= 1) {
            unsigned vc2 = __shfl_down_sync(0xffffffffu, sc, o);
            float    vv2 = __shfl_down_sync(0xffffffffu, sv, o);
            if (l + o < 32) { sc += vc2; sv += vv2; }
        }
        if (l == 0) { wt[w] = sc; wtf[w] = sv; }
        __syncthreads();
        unsigned wsufC = 0; float wsufS = 0.f;
        for (int w2 = w + 1; w2 < 8; w2++) { wsufC += wt[w2]; wsufS += wtf[w2]; }
        unsigned acc  = wsufC + (sc - lc);
        float    accS = wsufS + (sv - lv);
        unsigned Cab = g_Cab[a][b];
        float    Sab = g_Sab[a][b];
#pragma unroll
        for (int jj = 7; jj >= 0; jj--) {
            int i = t * 8 + jj;
            unsigned c = shc[i];
            unsigned ta = Cab + acc;           // exact count above entry i
            if (c > 0 && ta < (unsigned)kk && ta + c >= (unsigned)kk) {
                float mean = shs[i] / (float)c;
                float S = Sab + accS + (float)((unsigned)kk - ta) * mean;
                atomicAdd(out, 0.0625f * (S / ((float)kk + 1e-6f)));   // 0.5*loss/8
            }
            acc += c; accS += shs[i];
        }
    }
    __syncthreads();
    if (t == 0) {                              // self-clean scalars
        g_Sab[a][b] = 0.f; g_Cab[a][b] = 0u;
        if (a == 0) g_cntU[b] = 0u;
    }
}

extern "C" void kernel_launch(void* const* d_in, const int* in_sizes, int n_in,
                              void* d_out, int out_size) {
    const float4* img = (const float4*)d_in[0];
    const float4* alp = (const float4*)d_in[1];
    const float4* prd = (const float4*)d_in[2];
    const int4*   tri = (const int4*)  d_in[3];
    const float4* fg  = (const float4*)d_in[4];
    const float4* bg  = (const float4*)d_in[5];
    float* out = (float*)d_out;

    k1<<<(NB * NF4) / 256, 256>>>(img, alp, prd, tri, fg, bg, out);
    k2<<<16,              256>>>();
    k3<<<(NB * NF4) / 256, 256>>>();
    k4<<<16,              256>>>(out);
}

// round 10
// speedup vs baseline: 1.2893x; 1.2893x over previous
#include <cuda_runtime.h>
#include <stdint.h>

#define NB      8
#define NF4     65536             // float4 groups per sample
#define NBINS   2048
#define NTHR    256
#define GRID    296               // 2 blocks/SM * 148 (all-resident)
#define BPS     37                // blocks per sample
#define STRIDE  (BPS * NTHR)      // 9472
#define ITER    7                 // exact: 37*256*6 + 34*256 = 65536 (uniform per block)
#define MARGIN  4500              // ~17 sigma of 1/4-subsample count noise
#define SCALE_D 65535.0f          // d  in [0,1]
#define SCALE_C 21845.0f          // dc in [0,3]

__device__ unsigned g_hist1[2][NB][NBINS];  // subsampled linear-key histogram
__device__ unsigned g_win  [2][NB][NBINS];  // exact window counts
__device__ float    g_wsum [2][NB][NBINS];  // exact window sums
__device__ unsigned g_cntU [NB];
__device__ float    g_Sab  [2][NB];
__device__ unsigned g_Cab  [2][NB];
__device__ int      g_wlo  [2][NB];
__device__ int      g_whi  [2][NB];
__device__ unsigned g_bar  [4];             // monotonic epoch counters (never reset)

__device__ __forceinline__ unsigned f2bf(float f) {   // RNE f32->bf16 bits (nonneg finite)
    unsigned u = __float_as_uint(f);
    return (u + 0x7FFFu + ((u >> 16) & 1u)) >> 16;
}
__device__ __forceinline__ float bf2f(unsigned b) { return __uint_as_float(b << 16); }
__device__ __forceinline__ int   qkey(float v, float s) {
    int q = (int)(v * s);
    return q > 65535 ? 65535 : q;
}
__device__ __forceinline__ float pget(const float4& v, int p) { return p == 0 ? v.x : p == 1 ? v.y : p == 2 ? v.z : v.w; }
__device__ __forceinline__ int   tget(const int4&   v, int p) { return p == 0 ? v.x : p == 1 ? v.y : p == 2 ? v.z : v.w; }

__device__ __forceinline__ void grid_barrier(int id) {
    __syncthreads();
    if (threadIdx.x == 0) {
        __threadfence();
        unsigned old = atomicAdd(&g_bar[id], 1u);
        unsigned target = old - (old % GRID) + GRID;
        while (*((volatile unsigned*)&g_bar[id]) < target) __nanosleep(128);
        __threadfence();
    }
    __syncthreads();
}

__global__ void __launch_bounds__(NTHR, 2)   // 128-reg budget: ptxas batches the 15 loads
kFused(const float4* __restrict__ img, const float4* __restrict__ alp,
       const float4* __restrict__ prd, const int4*   __restrict__ tri,
       const float4* __restrict__ fg,  const float4* __restrict__ bg,
       float* out)
{
    __shared__ unsigned wt[8];
    __shared__ float    wtf[8];
    __shared__ unsigned s_ru[8];
    __shared__ float    s_rf0[8], s_rf1[8];
    __shared__ unsigned s_rc0[8], s_rc1[8];
    __shared__ int      s_w[2][2];           // [array][lo/hi]

    const int t   = threadIdx.x;
    const int l   = t & 31, w = t >> 5;
    const int blk = blockIdx.x;
    const int b   = blk / BPS;
    const int lb  = blk - b * BPS;
    const int cb  = b * 3 * NF4;

    if (blk == 0 && t == 0) out[0] = 0.0f;

    // ========== PHASE 1: load+compute; values stay in registers =============
    unsigned packed[ITER][4];
    unsigned cnt = 0;
    const float inv255 = 1.0f / 255.0f;
#pragma unroll
    for (int j = 0; j < ITER; j++) {
        int gl = lb * NTHR + t + j * STRIDE;
        if (gl >= NF4) {                      // only j==6, lb>=34: uniform per block
#pragma unroll
            for (int p = 0; p < 4; p++) packed[j][p] = 0u;
            continue;
        }
        int g = b * NF4 + gl;
        int4   tv = tri[g];
        float4 av = alp[g], pv = prd[g];
        float4 i0 = img[cb + gl], i1 = img[cb + NF4 + gl], i2 = img[cb + 2 * NF4 + gl];
        float4 f0 = fg [cb + gl], f1 = fg [cb + NF4 + gl], f2 = fg [cb + 2 * NF4 + gl];
        float4 g0 = bg [cb + gl], g1 = bg [cb + NF4 + gl], g2 = bg [cb + 2 * NF4 + gl];
        float d0 = 0.f, dc0 = 0.f; bool u0 = false;
#pragma unroll
        for (int p = 0; p < 4; p++) {
            bool u = (tget(tv, p) == 128);
            float pr = pget(pv, p), q = 1.0f - pr;
            float d = 0.0f, dc = 0.0f;
            if (u) {
                d  = fabsf(pget(av, p) * inv255 - pr);
                dc = fabsf(pget(i0, p) - (pget(f0, p) * pr + q * pget(g0, p)))
                   + fabsf(pget(i1, p) - (pget(f1, p) * pr + q * pget(g1, p)))
                   + fabsf(pget(i2, p) - (pget(f2, p) * pr + q * pget(g2, p)));
                cnt++;
            }
            if (p == 0) { u0 = u; d0 = d; dc0 = dc; }
            packed[j][p] = f2bf(d) | (f2bf(dc) << 16);
        }
        if (u0) {                              // 1/4 subsample, linear keys: spread REDG
            atomicAdd(&g_hist1[0][b][qkey(d0,  SCALE_D) >> 5], 1u);
            atomicAdd(&g_hist1[1][b][qkey(dc0, SCALE_C) >> 5], 1u);
        }
    }
    for (int o = 16; o; o >>= 1) cnt += __shfl_down_sync(0xffffffffu, cnt, o);
    if (l == 0) s_ru[w] = cnt;
    __syncthreads();
    if (t == 0) {
        unsigned tot = 0;
#pragma unroll
        for (int i = 0; i < 8; i++) tot += s_ru[i];
        atomicAdd(&g_cntU[b], tot);
    }

    grid_barrier(0);

    // ========== SELECT: every block derives conservative window for own b ===
    unsigned count = g_cntU[b];
    int k = (int)floorf((float)count * 0.7f);
    if (t == 0) { s_w[0][0] = 2047; s_w[0][1] = -1; s_w[1][0] = 2047; s_w[1][1] = -1; }
    __syncthreads();

    if (k > 0) {
#pragma unroll
        for (int a = 0; a < 2; a++) {
            unsigned harr[8];
            unsigned loc = 0;
#pragma unroll
            for (int jj = 0; jj < 8; jj++) { harr[jj] = g_hist1[a][b][t * 8 + jj]; loc += harr[jj]; }
            unsigned s = loc;
#pragma unroll
            for (int o = 1; o < 32; o <<= 1) {      // warp inclusive suffix scan
                unsigned v = __shfl_down_sync(0xffffffffu, s, o);
                if (l + o < 32) s += v;
            }
            if (l == 0) wt[w] = s;
            __syncthreads();
            unsigned wsuf = 0;
            for (int w2 = w + 1; w2 < 8; w2++) wsuf += wt[w2];
            int acc = (int)(wsuf + (s - loc));      // subsampled count above bin t*8+7
            int tLo = k + MARGIN;
            int tHi = max(k - MARGIN, 1);
#pragma unroll
            for (int jj = 7; jj >= 0; jj--) {
                int i = t * 8 + jj;
                int c = (int)harr[jj];
                int above  = 4 * acc;               // est exact count above bin i
                int aboveP = 4 * (acc + c);         // est above bin i-1
                if (above < tLo && (i == 0 || aboveP >= tLo)) { s_w[a][0] = i; g_wlo[a][b] = i; }
                if (above < tHi && (i == 0 || aboveP >= tHi)) { s_w[a][1] = i; g_whi[a][b] = i; }
                acc += c;
            }
            __syncthreads();
        }
    } else if (t == 0) {
        g_wlo[0][b] = 2047; g_whi[0][b] = -1;
        g_wlo[1][b] = 2047; g_whi[1][b] = -1;
    }
    __syncthreads();

    // ========== PHASE 2: register re-walk — exact above-window + window hist =
    const int wloD = s_w[0][0], whiD = s_w[0][1];
    const int wloC = s_w[1][0], whiC = s_w[1][1];
    const int hiD = (whiD + 1) << 5, loD = max(wloD << 5, 1);
    const int hiC = (whiC + 1) << 5, loC = max(wloC << 5, 1);

    float s0 = 0.0f, s1 = 0.0f;
    unsigned c0 = 0, c1 = 0;
#pragma unroll
    for (int j = 0; j < ITER; j++)
#pragma unroll
        for (int p = 0; p < 4; p++) {
            float vd = bf2f(packed[j][p] & 0xFFFFu);
            float vc = bf2f(packed[j][p] >> 16);
            int kqd = qkey(vd, SCALE_D);
            int kqc = qkey(vc, SCALE_C);
            if (kqd >= hiD) { s0 += vd; c0++; }
            else if (kqd >= loD) {
                int idx = (kqd >> 5) - wloD;
                atomicAdd(&g_win[0][b][idx], 1u);
                atomicAdd(&g_wsum[0][b][idx], vd);
            }
            if (kqc >= hiC) { s1 += vc; c1++; }
            else if (kqc >= loC) {
                int idx = (kqc >> 5) - wloC;
                atomicAdd(&g_win[1][b][idx], 1u);
                atomicAdd(&g_wsum[1][b][idx], vc);
            }
        }
    for (int o = 16; o; o >>= 1) {
        s0 += __shfl_down_sync(0xffffffffu, s0, o);
        s1 += __shfl_down_sync(0xffffffffu, s1, o);
        c0 += __shfl_down_sync(0xffffffffu, c0, o);
        c1 += __shfl_down_sync(0xffffffffu, c1, o);
    }
    if (l == 0) { s_rf0[w] = s0; s_rf1[w] = s1; s_rc0[w] = c0; s_rc1[w] = c1; }
    __syncthreads();
    if (t == 0) {
        float a0 = 0.f, a1 = 0.f; unsigned b0 = 0, b1 = 0;
#pragma unroll
        for (int i = 0; i < 8; i++) { a0 += s_rf0[i]; a1 += s_rf1[i]; b0 += s_rc0[i]; b1 += s_rc1[i]; }
        atomicAdd(&g_Sab[0][b], a0);  atomicAdd(&g_Sab[1][b], a1);
        atomicAdd(&g_Cab[0][b], b0);  atomicAdd(&g_Cab[1][b], b1);
    }

    grid_barrier(1);

    // ========== FINALIZE (16 blocks, own-unit cleanup) / hist cleanup =======
    if (blk >= 16) {
        int gid = (blk - 16) * NTHR + t;
        if (gid < 2 * NB * NBINS) ((unsigned*)g_hist1)[gid] = 0u;
        return;
    }
    {
        int a = blk >> 3, bb = blk & 7;
        unsigned cc = g_cntU[bb];
        int kk = (int)floorf((float)cc * 0.7f);
        unsigned harr[8]; float hars[8];
#pragma unroll
        for (int jj = 0; jj < 8; jj++) {
            int i = t * 8 + jj;
            harr[jj] = g_win[a][bb][i];
            hars[jj] = g_wsum[a][bb][i];
            g_win[a][bb][i] = 0u;              // self-clean for next replay
            g_wsum[a][bb][i] = 0.f;
        }
        if (kk > 0) {
            unsigned lc = 0; float lv = 0.f;
#pragma unroll
            for (int jj = 0; jj < 8; jj++) { lc += harr[jj]; lv += hars[jj]; }
            unsigned sc = lc; float sv = lv;
#pragma unroll
            for (int o = 1; o < 32; o <<= 1) {
                unsigned vc2 = __shfl_down_sync(0xffffffffu, sc, o);
                float    vv2 = __shfl_down_sync(0xffffffffu, sv, o);
                if (l + o < 32) { sc += vc2; sv += vv2; }
            }
            if (l == 0) { wt[w] = sc; wtf[w] = sv; }
            __syncthreads();
            unsigned wsufC = 0; float wsufS = 0.f;
            for (int w2 = w + 1; w2 < 8; w2++) { wsufC += wt[w2]; wsufS += wtf[w2]; }
            unsigned acc  = wsufC + (sc - lc);
            float    accS = wsufS + (sv - lv);
            unsigned Cab = g_Cab[a][bb];
            float    Sab = g_Sab[a][bb];
#pragma unroll
            for (int jj = 7; jj >= 0; jj--) {
                unsigned c = harr[jj];
                unsigned ta = Cab + acc;       // exact count above entry
                if (c > 0 && ta < (unsigned)kk && ta + c >= (unsigned)kk) {
                    float mean = hars[jj] / (float)c;
                    float S = Sab + accS + (float)((unsigned)kk - ta) * mean;
                    atomicAdd(out, 0.0625f * (S / ((float)kk + 1e-6f)));  // 0.5*loss/8
                }
                acc += c; accS += hars[jj];
            }
        }
        __syncthreads();
        if (t == 0) {                          // self-clean scalars
            g_Sab[a][bb] = 0.f; g_Cab[a][bb] = 0u;
            if (a == 0) g_cntU[bb] = 0u;
        }
    }
}

extern "C" void kernel_launch(void* const* d_in, const int* in_sizes, int n_in,
                              void* d_out, int out_size) {
    const float4* img = (const float4*)d_in[0];
    const float4* alp = (const float4*)d_in[1];
    const float4* prd = (const float4*)d_in[2];
    const int4*   tri = (const int4*)  d_in[3];
    const float4* fg  = (const float4*)d_in[4];
    const float4* bg  = (const float4*)d_in[5];
    kFused<<<GRID, NTHR>>>(img, alp, prd, tri, fg, bg, (float*)d_out);
}